// round 14
// baseline (speedup 1.0000x reference)
#include <cuda_runtime.h>
#include <cstdint>
#include <cstddef>

// NF4-dequant GEMM, round 12: same architecture as R11 (prep kernels ->
// tf32 scratch; cp.async 3-stage pipeline; mma.sync tf32; CTA 128x128x32,
// warp 64x32, 2 CTAs/SM). Polish: hoisted LDSM base addresses, prefetched
// bias registers. smem floor == tensor floor ~= 2048 cyc/iter; we are at
// ~85% of it, so gains here are the remaining overlap slack only.

#define BM 128
#define BN 128
#define BK 32
#define THREADS 256
#define STAGES 3
#define ASZ (BM * BK * 4)                 // 16 KB
#define WSZ (BN * BK * 4)                 // 16 KB
#define STAGE_STRIDE (ASZ + WSZ)          // 32 KB
#define SMEM_TOTAL (STAGES * STAGE_STRIDE) // 96 KB

#define MAX_ELEMS (4096 * 4096)
__device__ float g_xs[MAX_ELEMS];         // x pre-converted to tf32 bits
__device__ float g_wt[MAX_ELEMS];         // W dequantized to tf32 bits

__constant__ float NF4_CODE[16] = {
    -1.0f, -0.6961928009986877f, -0.5250730514526367f, -0.39491748809814453f,
    -0.28444138169288635f, -0.18477343022823334f, -0.09105003625154495f, 0.0f,
    0.07958029955625534f, 0.16093020141124725f, 0.24611230194568634f,
    0.33791524171829224f, 0.44070982933044434f, 0.5626170039176941f,
    0.6797559261322021f, 1.0f};

// ---------- helpers ----------
__device__ __forceinline__ uint32_t smem_u32(const void* p) {
    uint32_t a;
    asm("{ .reg .u64 t; cvta.to.shared.u64 t, %1; cvt.u32.u64 %0, t; }"
        : "=r"(a) : "l"(p));
    return a;
}

__device__ __forceinline__ uint32_t f2tf32(float f) {
    uint32_t r;
    asm("cvt.rn.tf32.f32 %0, %1;" : "=r"(r) : "f"(f));
    return r;
}

__device__ __forceinline__ void cp16(uint32_t saddr, const void* gptr) {
    asm volatile("cp.async.cg.shared.global [%0], [%1], 16;"
                 :: "r"(saddr), "l"(gptr) : "memory");
}

__device__ __forceinline__ void cp_commit() {
    asm volatile("cp.async.commit_group;" ::: "memory");
}

template <int N>
__device__ __forceinline__ void cp_wait() {
    asm volatile("cp.async.wait_group %0;" :: "n"(N) : "memory");
}

__device__ __forceinline__ void ldsm4(uint32_t* d, uint32_t addr) {
    asm volatile("ldmatrix.sync.aligned.m8n8.x4.shared.b16 {%0,%1,%2,%3}, [%4];"
                 : "=r"(d[0]), "=r"(d[1]), "=r"(d[2]), "=r"(d[3]) : "r"(addr));
}

__device__ __forceinline__ void mma_tf32(float* c, const uint32_t* a,
                                         uint32_t b0, uint32_t b1) {
    asm volatile(
        "mma.sync.aligned.m16n8k8.row.col.f32.tf32.tf32.f32 "
        "{%0,%1,%2,%3}, {%4,%5,%6,%7}, {%8,%9}, {%0,%1,%2,%3};"
        : "+f"(c[0]), "+f"(c[1]), "+f"(c[2]), "+f"(c[3])
        : "r"(a[0]), "r"(a[1]), "r"(a[2]), "r"(a[3]), "r"(b0), "r"(b1));
}

// swizzled byte offset for (row, chunk16B) inside a [rows][BK] f32 tile
__device__ __forceinline__ uint32_t sw_off(uint32_t row, uint32_t chunk) {
    return row * (BK * 4) + ((chunk ^ (row & 7)) << 4);
}

// ---------- prep kernels ----------
__global__ __launch_bounds__(256)
void prep_x_kernel(const float* __restrict__ x, int n4) {
    int stride = gridDim.x * blockDim.x;
    for (int i = blockIdx.x * blockDim.x + threadIdx.x; i < n4; i += stride) {
        float4 v = ((const float4*)x)[i];
        uint4 o;
        o.x = f2tf32(v.x); o.y = f2tf32(v.y);
        o.z = f2tf32(v.z); o.w = f2tf32(v.w);
        ((uint4*)g_xs)[i] = o;
    }
}

__global__ __launch_bounds__(256)
void prep_w_kernel(const int* __restrict__ codes,
                   const float* __restrict__ absmax, int n4, int K) {
    int stride = gridDim.x * blockDim.x;
    const int kb = K >> 6;
    for (int i = blockIdx.x * blockDim.x + threadIdx.x; i < n4; i += stride) {
        int4 c = ((const int4*)codes)[i];
        int e = i << 2;
        int n = e / K, k = e - n * K;
        float sc = __ldg(absmax + (size_t)n * kb + (k >> 6));
        uint4 o;
        o.x = f2tf32(NF4_CODE[c.x & 15] * sc);
        o.y = f2tf32(NF4_CODE[c.y & 15] * sc);
        o.z = f2tf32(NF4_CODE[c.z & 15] * sc);
        o.w = f2tf32(NF4_CODE[c.w & 15] * sc);
        ((uint4*)g_wt)[i] = o;
    }
}

// ---------- GEMM kernel ----------
__global__ __launch_bounds__(THREADS, 2)
void nf4_mma4_kernel(const float* __restrict__ bias,
                     float* __restrict__ out,
                     int M, int N, int K) {
    extern __shared__ char smem[];
    const uint32_t sb = smem_u32(smem);

    const int t    = threadIdx.x;
    const int lane = t & 31;
    const int wid  = t >> 5;
    const int m0   = blockIdx.y * BM;
    const int n0   = blockIdx.x * BN;

    // warp position: 2 warps along M (64), 4 along N (32)
    const int wm = (wid & 1) * 64;
    const int wn = (wid >> 1) * 32;

    // ldmatrix lane geometry (same for A and B fragments)
    const int g     = lane >> 3;
    const int r_loc = (lane & 7) + ((g & 1) << 3);
    const int chalf = g >> 1;

    // hoisted LDSM addresses: offset within a tile for (row, chunk=chalf);
    // per-ks step advances by 2 chunks = 32B XORed into the swizzle pattern.
    uint32_t aOff[4], bOff[2];
    #pragma unroll
    for (int mt = 0; mt < 4; mt++)
        aOff[mt] = sw_off((uint32_t)(wm + mt * 16 + r_loc), (uint32_t)chalf);
    #pragma unroll
    for (int p = 0; p < 2; p++)
        bOff[p] = sw_off((uint32_t)(wn + p * 16 + r_loc), (uint32_t)chalf);

    // staging geometry: 8 threads per 128B row
    const int srow = t >> 3;
    const int schk = t & 7;

    const char* aBase[4];
    const char* wBase[4];
    #pragma unroll
    for (int l = 0; l < 4; l++) {
        aBase[l] = (const char*)(g_xs + (size_t)(m0 + srow + l * 32) * K + schk * 4);
        wBase[l] = (const char*)(g_wt + (size_t)(n0 + srow + l * 32) * K + schk * 4);
    }
    uint32_t swS[4];
    #pragma unroll
    for (int l = 0; l < 4; l++) swS[l] = sw_off(srow + l * 32, schk);

    // prefetch bias for this thread's 8 output columns
    const int qr = lane >> 2;
    const int qc = (lane & 3) << 1;
    float bv[4][2];
    #pragma unroll
    for (int nt = 0; nt < 4; nt++) {
        bv[nt][0] = __ldg(bias + n0 + wn + nt * 8 + qc);
        bv[nt][1] = __ldg(bias + n0 + wn + nt * 8 + qc + 1);
    }

    float acc[4][4][4];
    #pragma unroll
    for (int i = 0; i < 4; i++)
        #pragma unroll
        for (int j = 0; j < 4; j++)
            #pragma unroll
            for (int f = 0; f < 4; f++) acc[i][j][f] = 0.0f;

    const int NITER = K / BK;

    auto issue = [&](int st) {
        const uint32_t bufA = sb + (st % STAGES) * STAGE_STRIDE;
        const uint32_t bufW = bufA + ASZ;
        const size_t kOff = (size_t)(st * BK) * 4;
        #pragma unroll
        for (int l = 0; l < 4; l++) cp16(bufA + swS[l], aBase[l] + kOff);
        #pragma unroll
        for (int l = 0; l < 4; l++) cp16(bufW + swS[l], wBase[l] + kOff);
        cp_commit();
    };

    issue(0);
    issue(1);

    #pragma unroll 1
    for (int it = 0; it < NITER; it++) {
        if (it + 1 < NITER) cp_wait<1>(); else cp_wait<0>();
        __syncthreads();
        // safe: buffer (it+2)%3 == (it-1)%3, fully consumed once every warp
        // passed the barrier above.
        if (it + 2 < NITER) issue(it + 2);

        const uint32_t bufA = sb + (it % STAGES) * STAGE_STRIDE;
        const uint32_t bufW = bufA + ASZ;

        #pragma unroll
        for (int ks = 0; ks < 4; ks++) {
            // per-ks swizzle delta: ks*2 lives in bits [1:2] of the chunk
            // index, chalf in bit 0 -> chunk = (ks*2) ^ chalf, and XOR
            // distributes through the swizzle: offset = base ^ ((ks*2)<<4).
            const uint32_t kx = (uint32_t)(ks * 2) << 4;
            uint32_t bf[2][4];
            #pragma unroll
            for (int p = 0; p < 2; p++)
                ldsm4(bf[p], bufW + (bOff[p] ^ kx));
            #pragma unroll
            for (int mt = 0; mt < 4; mt++) {
                uint32_t af[4];
                ldsm4(af, bufA + (aOff[mt] ^ kx));
                #pragma unroll
                for (int nt = 0; nt < 4; nt++) {
                    const uint32_t* b = bf[nt >> 1];
                    mma_tf32(acc[mt][nt], af, b[nt & 1], b[2 + (nt & 1)]);
                }
            }
        }
    }

    // ---- epilogue ----
    #pragma unroll
    for (int nt = 0; nt < 4; nt++) {
        const int n = n0 + wn + nt * 8 + qc;
        const float b0 = bv[nt][0];
        const float b1 = bv[nt][1];
        #pragma unroll
        for (int mt = 0; mt < 4; mt++) {
            const int mrow = m0 + wm + mt * 16 + qr;
            float v0 = acc[mt][nt][0] + b0;
            float v1 = acc[mt][nt][1] + b1;
            float v2 = acc[mt][nt][2] + b0;
            float v3 = acc[mt][nt][3] + b1;
            v0 = ((__float_as_uint(v0) & 0x7f800000u) == 0x7f800000u) ? 0.0f : v0;
            v1 = ((__float_as_uint(v1) & 0x7f800000u) == 0x7f800000u) ? 0.0f : v1;
            v2 = ((__float_as_uint(v2) & 0x7f800000u) == 0x7f800000u) ? 0.0f : v2;
            v3 = ((__float_as_uint(v3) & 0x7f800000u) == 0x7f800000u) ? 0.0f : v3;
            *(float2*)(out + (size_t)mrow * N + n)       = make_float2(v0, v1);
            *(float2*)(out + (size_t)(mrow + 8) * N + n) = make_float2(v2, v3);
        }
    }
}

extern "C" void kernel_launch(void* const* d_in, const int* in_sizes, int n_in,
                              void* d_out, int out_size) {
    const float* x      = (const float*)d_in[0];
    const int*   codes  = (const int*)d_in[1];
    const float* absmax = (const float*)d_in[2];
    const float* bias   = (const float*)d_in[3];
    float*       out    = (float*)d_out;

    const int N = in_sizes[3];                                   // OUT
    const int K = (int)(((long long)in_sizes[2] * 64) / N);      // IN
    const int M = in_sizes[0] / K;                               // B*S

    prep_x_kernel<<<4096, 256>>>(x, in_sizes[0] / 4);
    prep_w_kernel<<<4096, 256>>>(codes, absmax, in_sizes[1] / 4, K);

    cudaFuncSetAttribute(nf4_mma4_kernel,
                         cudaFuncAttributeMaxDynamicSharedMemorySize, SMEM_TOTAL);
    dim3 grid(N / BN, M / BM);
    nf4_mma4_kernel<<<grid, THREADS, SMEM_TOTAL>>>(bias, out, M, N, K);
}

// round 17
// speedup vs baseline: 1.0400x; 1.0400x over previous
#include <cuda_runtime.h>
#include <cstdint>
#include <cstddef>

// NF4-dequant GEMM — FINAL (R11 configuration, re-validated).
// prep kernels (x->tf32, W dequant->tf32 in __device__ scratch) +
// cp.async 3-stage pipelined mma.sync tf32 GEMM.
// CTA 128x128x32, warp tile 64x32, __launch_bounds__(256,2) -> 2 CTAs/SM.
// R14 showed the hoisted-address/bias-prefetch polish REGRESSES (+4%) via
// register pressure at the 128-reg cap; this reverts to the 817us version.

#define BM 128
#define BN 128
#define BK 32
#define THREADS 256
#define STAGES 3
#define ASZ (BM * BK * 4)                 // 16 KB
#define WSZ (BN * BK * 4)                 // 16 KB
#define STAGE_STRIDE (ASZ + WSZ)          // 32 KB
#define SMEM_TOTAL (STAGES * STAGE_STRIDE) // 96 KB

#define MAX_ELEMS (4096 * 4096)
__device__ float g_xs[MAX_ELEMS];         // x pre-converted to tf32 bits
__device__ float g_wt[MAX_ELEMS];         // W dequantized to tf32 bits

__constant__ float NF4_CODE[16] = {
    -1.0f, -0.6961928009986877f, -0.5250730514526367f, -0.39491748809814453f,
    -0.28444138169288635f, -0.18477343022823334f, -0.09105003625154495f, 0.0f,
    0.07958029955625534f, 0.16093020141124725f, 0.24611230194568634f,
    0.33791524171829224f, 0.44070982933044434f, 0.5626170039176941f,
    0.6797559261322021f, 1.0f};

// ---------- helpers ----------
__device__ __forceinline__ uint32_t smem_u32(const void* p) {
    uint32_t a;
    asm("{ .reg .u64 t; cvta.to.shared.u64 t, %1; cvt.u32.u64 %0, t; }"
        : "=r"(a) : "l"(p));
    return a;
}

__device__ __forceinline__ uint32_t f2tf32(float f) {
    uint32_t r;
    asm("cvt.rn.tf32.f32 %0, %1;" : "=r"(r) : "f"(f));
    return r;
}

__device__ __forceinline__ void cp16(uint32_t saddr, const void* gptr) {
    asm volatile("cp.async.cg.shared.global [%0], [%1], 16;"
                 :: "r"(saddr), "l"(gptr) : "memory");
}

__device__ __forceinline__ void cp_commit() {
    asm volatile("cp.async.commit_group;" ::: "memory");
}

template <int N>
__device__ __forceinline__ void cp_wait() {
    asm volatile("cp.async.wait_group %0;" :: "n"(N) : "memory");
}

__device__ __forceinline__ void ldsm4(uint32_t* d, uint32_t addr) {
    asm volatile("ldmatrix.sync.aligned.m8n8.x4.shared.b16 {%0,%1,%2,%3}, [%4];"
                 : "=r"(d[0]), "=r"(d[1]), "=r"(d[2]), "=r"(d[3]) : "r"(addr));
}

__device__ __forceinline__ void mma_tf32(float* c, const uint32_t* a,
                                         uint32_t b0, uint32_t b1) {
    asm volatile(
        "mma.sync.aligned.m16n8k8.row.col.f32.tf32.tf32.f32 "
        "{%0,%1,%2,%3}, {%4,%5,%6,%7}, {%8,%9}, {%0,%1,%2,%3};"
        : "+f"(c[0]), "+f"(c[1]), "+f"(c[2]), "+f"(c[3])
        : "r"(a[0]), "r"(a[1]), "r"(a[2]), "r"(a[3]), "r"(b0), "r"(b1));
}

// swizzled byte offset for (row, chunk16B) inside a [rows][BK] f32 tile
__device__ __forceinline__ uint32_t sw_off(uint32_t row, uint32_t chunk) {
    return row * (BK * 4) + ((chunk ^ (row & 7)) << 4);
}

// ---------- prep kernels ----------
__global__ __launch_bounds__(256)
void prep_x_kernel(const float* __restrict__ x, int n4) {
    int stride = gridDim.x * blockDim.x;
    for (int i = blockIdx.x * blockDim.x + threadIdx.x; i < n4; i += stride) {
        float4 v = ((const float4*)x)[i];
        uint4 o;
        o.x = f2tf32(v.x); o.y = f2tf32(v.y);
        o.z = f2tf32(v.z); o.w = f2tf32(v.w);
        ((uint4*)g_xs)[i] = o;
    }
}

__global__ __launch_bounds__(256)
void prep_w_kernel(const int* __restrict__ codes,
                   const float* __restrict__ absmax, int n4, int K) {
    int stride = gridDim.x * blockDim.x;
    const int kb = K >> 6;
    for (int i = blockIdx.x * blockDim.x + threadIdx.x; i < n4; i += stride) {
        int4 c = ((const int4*)codes)[i];
        int e = i << 2;
        int n = e / K, k = e - n * K;
        float sc = __ldg(absmax + (size_t)n * kb + (k >> 6));
        uint4 o;
        o.x = f2tf32(NF4_CODE[c.x & 15] * sc);
        o.y = f2tf32(NF4_CODE[c.y & 15] * sc);
        o.z = f2tf32(NF4_CODE[c.z & 15] * sc);
        o.w = f2tf32(NF4_CODE[c.w & 15] * sc);
        ((uint4*)g_wt)[i] = o;
    }
}

// ---------- GEMM kernel ----------
__global__ __launch_bounds__(THREADS, 2)
void nf4_mma3_kernel(const float* __restrict__ bias,
                     float* __restrict__ out,
                     int M, int N, int K) {
    extern __shared__ char smem[];
    const uint32_t sb = smem_u32(smem);

    const int t    = threadIdx.x;
    const int lane = t & 31;
    const int wid  = t >> 5;
    const int m0   = blockIdx.y * BM;
    const int n0   = blockIdx.x * BN;

    // warp position: 2 warps along M (64), 4 along N (32)
    const int wm = (wid & 1) * 64;
    const int wn = (wid >> 1) * 32;

    // ldmatrix lane geometry (same for A and B fragments)
    const int g     = lane >> 3;
    const int r_loc = (lane & 7) + ((g & 1) << 3);
    const int chalf = g >> 1;

    // staging geometry: 8 threads per 128B row
    const int srow = t >> 3;              // 0..31, +32 per l
    const int schk = t & 7;

    const char* aBase[4];
    const char* wBase[4];
    #pragma unroll
    for (int l = 0; l < 4; l++) {
        aBase[l] = (const char*)(g_xs + (size_t)(m0 + srow + l * 32) * K + schk * 4);
        wBase[l] = (const char*)(g_wt + (size_t)(n0 + srow + l * 32) * K + schk * 4);
    }
    uint32_t swS[4];
    #pragma unroll
    for (int l = 0; l < 4; l++) swS[l] = sw_off(srow + l * 32, schk);

    float acc[4][4][4];
    #pragma unroll
    for (int i = 0; i < 4; i++)
        #pragma unroll
        for (int j = 0; j < 4; j++)
            #pragma unroll
            for (int f = 0; f < 4; f++) acc[i][j][f] = 0.0f;

    const int NITER = K / BK;

    auto issue = [&](int st) {
        const uint32_t bufA = sb + (st % STAGES) * STAGE_STRIDE;
        const uint32_t bufW = bufA + ASZ;
        const size_t kOff = (size_t)(st * BK) * 4;
        #pragma unroll
        for (int l = 0; l < 4; l++) cp16(bufA + swS[l], aBase[l] + kOff);
        #pragma unroll
        for (int l = 0; l < 4; l++) cp16(bufW + swS[l], wBase[l] + kOff);
        cp_commit();
    };

    issue(0);
    issue(1);

    #pragma unroll 1
    for (int it = 0; it < NITER; it++) {
        if (it + 1 < NITER) cp_wait<1>(); else cp_wait<0>();
        __syncthreads();
        // safe: buffer (it+2)%3 == (it-1)%3, fully consumed once every warp
        // passed the barrier above (they all finished compute of it-1).
        if (it + 2 < NITER) issue(it + 2);

        const uint32_t bufA = sb + (it % STAGES) * STAGE_STRIDE;
        const uint32_t bufW = bufA + ASZ;

        #pragma unroll
        for (int ks = 0; ks < 4; ks++) {
            const uint32_t chunk = (uint32_t)(ks * 2 + chalf);
            uint32_t bf[2][4];
            #pragma unroll
            for (int p = 0; p < 2; p++)
                ldsm4(bf[p], bufW + sw_off((uint32_t)(wn + p * 16 + r_loc), chunk));
            #pragma unroll
            for (int mt = 0; mt < 4; mt++) {
                uint32_t af[4];
                ldsm4(af, bufA + sw_off((uint32_t)(wm + mt * 16 + r_loc), chunk));
                #pragma unroll
                for (int nt = 0; nt < 4; nt++) {
                    const uint32_t* b = bf[nt >> 1];
                    mma_tf32(acc[mt][nt], af, b[nt & 1], b[2 + (nt & 1)]);
                }
            }
        }
    }

    // ---- epilogue ----
    const int qr = lane >> 2;
    const int qc = (lane & 3) << 1;

    #pragma unroll
    for (int nt = 0; nt < 4; nt++) {
        const int n = n0 + wn + nt * 8 + qc;
        const float b0 = __ldg(bias + n);
        const float b1 = __ldg(bias + n + 1);
        #pragma unroll
        for (int mt = 0; mt < 4; mt++) {
            const int mrow = m0 + wm + mt * 16 + qr;
            float v0 = acc[mt][nt][0] + b0;
            float v1 = acc[mt][nt][1] + b1;
            float v2 = acc[mt][nt][2] + b0;
            float v3 = acc[mt][nt][3] + b1;
            v0 = ((__float_as_uint(v0) & 0x7f800000u) == 0x7f800000u) ? 0.0f : v0;
            v1 = ((__float_as_uint(v1) & 0x7f800000u) == 0x7f800000u) ? 0.0f : v1;
            v2 = ((__float_as_uint(v2) & 0x7f800000u) == 0x7f800000u) ? 0.0f : v2;
            v3 = ((__float_as_uint(v3) & 0x7f800000u) == 0x7f800000u) ? 0.0f : v3;
            *(float2*)(out + (size_t)mrow * N + n)       = make_float2(v0, v1);
            *(float2*)(out + (size_t)(mrow + 8) * N + n) = make_float2(v2, v3);
        }
    }
}

extern "C" void kernel_launch(void* const* d_in, const int* in_sizes, int n_in,
                              void* d_out, int out_size) {
    const float* x      = (const float*)d_in[0];
    const int*   codes  = (const int*)d_in[1];
    const float* absmax = (const float*)d_in[2];
    const float* bias   = (const float*)d_in[3];
    float*       out    = (float*)d_out;

    const int N = in_sizes[3];                                   // OUT
    const int K = (int)(((long long)in_sizes[2] * 64) / N);      // IN
    const int M = in_sizes[0] / K;                               // B*S

    prep_x_kernel<<<4096, 256>>>(x, in_sizes[0] / 4);
    prep_w_kernel<<<4096, 256>>>(codes, absmax, in_sizes[1] / 4, K);

    cudaFuncSetAttribute(nf4_mma3_kernel,
                         cudaFuncAttributeMaxDynamicSharedMemorySize, SMEM_TOTAL);
    dim3 grid(N / BN, M / BM);
    nf4_mma3_kernel<<<grid, THREADS, SMEM_TOTAL>>>(bias, out, M, N, K);
}